// round 8
// baseline (speedup 1.0000x reference)
#include <cuda_runtime.h>
#include <cuda_bf16.h>
#include <cstdint>
#include <math.h>

// ============================================================================
// Tree-GRU via mma.sync (HMMA) bf16 3-term split GEMMs.  B=32, L=4096, D=256.
// R8: term-major MMA passes (dependency distance 8), non-volatile mma asm.
// A = [x | h] (K=512) bf16 hi/lo;  W = [term][dblk][192][512] bf16.
// Gate warps (nb): r(all K), z(all K), i_n(K<256), h_n(K>=256).
// ============================================================================

#define DH 256
#define MROWS_MAX 65536
#define ASTRIDE ((size_t)MROWS_MAX * 512)          // elems per term
#define ABYTES  (ASTRIDE * 2)                      // bytes per term
#define WSTRIDE ((size_t)4 * 192 * 512)
#define WBYTES  (WSTRIDE * 2)

__device__ __nv_bfloat16 g_A1[2 * ASTRIDE];    // [term][m][512]
__device__ __nv_bfloat16 g_A2a[2 * ASTRIDE];
__device__ __nv_bfloat16 g_A2b[2 * ASTRIDE];
__device__ __nv_bfloat16 g_Wb[2 * WSTRIDE];

// ---------------- PTX helpers ----------------
__device__ __forceinline__ uint32_t smem_u32(const void* p) {
    uint32_t a;
    asm("{ .reg .u64 t; cvta.to.shared.u64 t, %1; cvt.u32.u64 %0, t; }"
        : "=r"(a) : "l"(p));
    return a;
}
__device__ __forceinline__ void cpasync16(uint32_t dst, const void* src) {
    asm volatile("cp.async.cg.shared.global [%0], [%1], 16;"
                 :: "r"(dst), "l"(src) : "memory");
}
__device__ __forceinline__ void cpcommit() {
    asm volatile("cp.async.commit_group;" ::: "memory");
}
template<int N>
__device__ __forceinline__ void cpwait() {
    asm volatile("cp.async.wait_group %0;" :: "n"(N) : "memory");
}
__device__ __forceinline__ void ldsm4(uint32_t r[4], uint32_t addr) {
    asm volatile("ldmatrix.sync.aligned.m8n8.x4.shared.b16 {%0,%1,%2,%3}, [%4];"
                 : "=r"(r[0]), "=r"(r[1]), "=r"(r[2]), "=r"(r[3]) : "r"(addr));
}
// NOTE: non-volatile — register-only op, deps carried by constraints; lets
// ptxas interleave/pipeline the HMMA stream.
__device__ __forceinline__ void mma16816(float c[4], const uint32_t a[4],
                                         uint32_t b0, uint32_t b1) {
    asm("mma.sync.aligned.m16n8k16.row.col.f32.bf16.bf16.f32 "
        "{%0,%1,%2,%3}, {%4,%5,%6,%7}, {%8,%9}, {%0,%1,%2,%3};"
        : "+f"(c[0]), "+f"(c[1]), "+f"(c[2]), "+f"(c[3])
        : "r"(a[0]), "r"(a[1]), "r"(a[2]), "r"(a[3]),
          "r"(b0), "r"(b1));
}
#define SW64(x) ((x) ^ (((x) >> 3) & 0x30))

// ---------------- math helpers ----------------
__device__ __forceinline__ float sigacc(float x) { return 1.f / (1.f + expf(-x)); }
__device__ __forceinline__ float tanhacc(float x) {
    float ax = fabsf(x);
    float t = expf(-2.f * ax);
    float r = (1.f - t) / (1.f + t);
    return (x < 0.f) ? -r : r;
}
__device__ __forceinline__ uint32_t pk2(float a, float b) {
    __nv_bfloat162 h = __floats2bfloat162_rn(a, b);
    return *(uint32_t*)&h;
}
__device__ __forceinline__ float2 ub2(uint32_t u) {
    __nv_bfloat162 h = *(__nv_bfloat162*)&u;
    return make_float2(__bfloat162float(h.x), __bfloat162float(h.y));
}
__device__ __forceinline__ void split1(float v, float& hi, float& lo) {
    __nv_bfloat16 h = __float2bfloat16(v);
    hi = __bfloat162float(h);
    lo = v - hi;
}
__device__ __forceinline__ void split4(float4 v, uint2& hi, uint2& lo) {
    float hx, lx, hy, ly, hz, lz, hw, lw;
    split1(v.x, hx, lx); split1(v.y, hy, ly);
    split1(v.z, hz, lz); split1(v.w, hw, lw);
    hi = make_uint2(pk2(hx, hy), pk2(hz, hw));
    lo = make_uint2(pk2(lx, ly), pk2(lz, lw));
}
// write 16 floats as bf16 hi (32B at p) + lo (32B at p+ABYTES)
__device__ __forceinline__ void wsplit16(char* p, const float* v) {
    #pragma unroll
    for (int h = 0; h < 2; ++h) {
        uint4 vh, vl;
        uint32_t* ph = &vh.x;
        uint32_t* pl = &vl.x;
        #pragma unroll
        for (int q = 0; q < 4; ++q) {
            float a_hi, a_lo, b_hi, b_lo;
            split1(v[h * 8 + 2 * q], a_hi, a_lo);
            split1(v[h * 8 + 2 * q + 1], b_hi, b_lo);
            ph[q] = pk2(a_hi, b_hi);
            pl[q] = pk2(a_lo, b_lo);
        }
        *(uint4*)(p + h * 16) = vh;
        *(uint4*)(p + ABYTES + h * 16) = vl;
    }
}
// read 16 dims of hi+lo split back to fp32
__device__ __forceinline__ void rsplit16(const char* p, float* v) {
    #pragma unroll
    for (int h = 0; h < 2; ++h) {
        uint4 vh = *(const uint4*)(p + h * 16);
        uint4 vl = *(const uint4*)(p + ABYTES + h * 16);
        const uint32_t* ph = &vh.x;
        const uint32_t* pl = &vl.x;
        #pragma unroll
        for (int q = 0; q < 4; ++q) {
            float2 a = ub2(ph[q]), b = ub2(pl[q]);
            v[h * 8 + 2 * q]     = a.x + b.x;
            v[h * 8 + 2 * q + 1] = a.y + b.y;
        }
    }
}

// ---------------- weight prep: g_Wb[term][dblk][gate*64+dd][k] ----------------
__global__ void wprep(const float* __restrict__ wih, const float* __restrict__ whh) {
    int idx = blockIdx.x * blockDim.x + threadIdx.x;
    if (idx >= 4 * 192 * 512) return;
    int k = idx & 511;
    int rowall = idx >> 9;
    int blk = rowall / 192;
    int rr = rowall - blk * 192;
    int gate = rr >> 6;
    int dd = rr & 63;
    int g = gate * 256 + blk * 64 + dd;
    float v = (k < 256) ? wih[g * 256 + k] : whh[g * 256 + (k - 256)];
    float hi, lo; split1(v, hi, lo);
    g_Wb[idx] = __float2bfloat16(hi);
    g_Wb[WSTRIDE + idx] = __float2bfloat16(lo);
}

// ---------------- level-0 prep: leaf -> A1 (xL, h=0), A2a (xR) ----------------
__global__ void prep0(const float* __restrict__ emb, int M) {
    int idx = blockIdx.x * blockDim.x + threadIdx.x;   // M*128
    if (idx >= M * 128) return;
    int m = idx >> 7;
    int kq = idx & 127;
    size_t rowL = ((size_t)(2 * m)) * 256;   // lgP=11, n=4096: b*4096+2j = 2m
    char* A1 = (char*)g_A1;
    char* A2 = (char*)g_A2a;
    if (kq < 64) {
        int k = kq * 4;
        float4 xl = *(const float4*)(emb + rowL + k);
        float4 xr = *(const float4*)(emb + rowL + 256 + k);
        uint2 hi, lo;
        size_t off = (size_t)m * 1024 + (size_t)k * 2;
        split4(xl, hi, lo);
        *(uint2*)(A1 + off) = hi;
        *(uint2*)(A1 + ABYTES + off) = lo;
        split4(xr, hi, lo);
        *(uint2*)(A2 + off) = hi;
        *(uint2*)(A2 + ABYTES + off) = lo;
    } else {
        int k = (kq - 64) * 4;
        size_t off = (size_t)m * 1024 + 512 + (size_t)k * 2;
        *(uint2*)(A1 + off) = make_uint2(0u, 0u);
        *(uint2*)(A1 + ABYTES + off) = make_uint2(0u, 0u);
    }
}

// ---------------- GEMM cell kernel ----------------
// smem: 4 staging buffers x 40960B (Ahi 8K | Alo 8K | Whi 12K | Wlo 12K).
// Epilogue overlays 4 gate planes [128][68] f32 (34816B each) at 0,
// ho plane at 139264, bias (256 f32) at 174080.
#define SM_BUFSZ 40960
#define PLANE_B 34816
#define PLANE_F 8704
#define SM_HOPL 139264
#define SM_BIAS 174080
#define SM_TOTAL 175104

template<int MODE>
__global__ __launch_bounds__(512, 1) void gemm_cell(
    const __nv_bfloat16* __restrict__ Abase,
    const float* __restrict__ bih, const float* __restrict__ bhh,
    __nv_bfloat16* __restrict__ Hw,            // MODE0: h1 split dest (A2cur h-part)
    __nv_bfloat16* __restrict__ A1n,           // MODE1: next-level A1 (or null)
    __nv_bfloat16* __restrict__ A2n,           // MODE1: next-level A2
    float* __restrict__ embOut,                // MODE1 level 11 only
    int M)
{
    extern __shared__ char smem[];
    const uint32_t sbt = smem_u32(smem);
    const int t = threadIdx.x;
    const int lane = t & 31, wid = t >> 5;
    const int mi = wid & 3, nb = wid >> 2;     // nb: 0=r 1=z 2=i_n 3=h_n
    const int rowBase = blockIdx.x * 128;
    const int dblk = blockIdx.y;
    const int d0g = dblk * 64;
    const char* Ab = (const char*)Abase;

    // stage combined biases
    if (t < 64) {
        int dg = d0g + t;
        float* bs = (float*)(smem + SM_BIAS);
        bs[t]       = bih[dg] + bhh[dg];
        bs[64 + t]  = bih[256 + dg] + bhh[256 + dg];
        bs[128 + t] = bih[512 + dg];
        bs[192 + t] = bhh[512 + dg];
    }

    // ---- precompute 5 staging slots per thread (2560 x 16B per chunk) ----
    const char *s0, *s1, *s2, *s3, *s4;
    uint32_t dst0, dst1, dst2, dst3, dst4;
    {
        // slots 0,1: A (2 terms x 128 rows x 4 segs)
        #pragma unroll
        for (int p = 0; p < 2; ++p) {
            int u = t + 512 * p;
            int term = u >> 9, rem = u & 511, row = rem >> 2, seg = rem & 3;
            const char* sp = Ab + (size_t)term * ABYTES +
                             (size_t)(rowBase + row) * 1024 + seg * 16;
            uint32_t d = term * 8192 + SW64(row * 64 + seg * 16);
            if (p == 0) { s0 = sp; dst0 = d; } else { s1 = sp; dst1 = d; }
        }
        // slots 2-4: W (2 terms x 192 rows x 4 segs)
        #pragma unroll
        for (int p = 2; p < 5; ++p) {
            int v = t + 512 * p - 1024;
            int term = (v >= 768) ? 1 : 0;
            int rem = v - term * 768, row = rem >> 2, seg = rem & 3;
            const char* sp = (const char*)g_Wb + (size_t)term * WBYTES +
                             (size_t)(dblk * 192 + row) * 1024 + seg * 16;
            uint32_t d = 16384 + term * 12288 + SW64(row * 64 + seg * 16);
            if (p == 2) { s2 = sp; dst2 = d; }
            else if (p == 3) { s3 = sp; dst3 = d; }
            else { s4 = sp; dst4 = d; }
        }
    }
#define STAGE(bi) do { uint32_t bb = sbt + (bi) * SM_BUFSZ;           \
        cpasync16(bb + dst0, s0); s0 += 64;                            \
        cpasync16(bb + dst1, s1); s1 += 64;                            \
        cpasync16(bb + dst2, s2); s2 += 64;                            \
        cpasync16(bb + dst3, s3); s3 += 64;                            \
        cpasync16(bb + dst4, s4); s4 += 64; } while (0)

    // ---- ldsm address precompute ----
    const int rsel = lane & 15, half = lane >> 4;
    const int m0 = mi * 32;
    const int wrow = (nb >= 2) ? 128 : nb * 64;
    const int rA0 = m0 + rsel,      aoff0 = rA0 * 64, ax0 = (rA0 >> 1) & 3;
    const int rA1 = m0 + 16 + rsel, aoff1 = rA1 * 64, ax1 = (rA1 >> 1) & 3;
    int boff[4], bx[4];
    #pragma unroll
    for (int n16 = 0; n16 < 4; ++n16) {
        int rB = wrow + n16 * 16 + rsel;
        boff[n16] = rB * 64;
        bx[n16] = (rB >> 1) & 3;
    }

    float acc[2][8][4];
    #pragma unroll
    for (int a = 0; a < 2; ++a)
        #pragma unroll
        for (int b = 0; b < 8; ++b)
            #pragma unroll
            for (int e = 0; e < 4; ++e) acc[a][b][e] = 0.f;

    STAGE(0); cpcommit();
    STAGE(1); cpcommit();
    STAGE(2); cpcommit();

    for (int c = 0; c < 16; ++c) {
        __syncthreads();                       // buf (c-1)&3 readers done
        if (c < 13) STAGE((c + 3) & 3);
        cpcommit();
        cpwait<3>();
        __syncthreads();                       // chunk c visible to all
        bool act = (nb < 2) || (nb == 2 && c < 8) || (nb == 3 && c >= 8);
        if (act) {
            uint32_t bb = sbt + (c & 3) * SM_BUFSZ;
            uint32_t bA = bb, bAl = bb + 8192, bW = bb + 16384, bWl = bb + 28672;
            #pragma unroll
            for (int kb = 0; kb < 2; ++kb) {
                int sg = 2 * kb + half;
                uint32_t ah[2][4], al[2][4];
                ldsm4(ah[0], bA  + aoff0 + ((sg ^ ax0) << 4));
                ldsm4(ah[1], bA  + aoff1 + ((sg ^ ax1) << 4));
                ldsm4(al[0], bAl + aoff0 + ((sg ^ ax0) << 4));
                ldsm4(al[1], bAl + aoff1 + ((sg ^ ax1) << 4));
                #pragma unroll
                for (int nh = 0; nh < 2; ++nh) {   // n16 pairs {0,1},{2,3}
                    uint32_t bh[2][4], bl[2][4];
                    #pragma unroll
                    for (int n2 = 0; n2 < 2; ++n2) {
                        int n16 = nh * 2 + n2;
                        uint32_t wo = ((sg ^ bx[n16]) << 4) + boff[n16];
                        ldsm4(bh[n2], bW + wo);
                        ldsm4(bl[n2], bWl + wo);
                    }
                    // pass 1: A_hi x B_hi  (8 mmas, 8 distinct accumulators)
                    #pragma unroll
                    for (int n2 = 0; n2 < 2; ++n2)
                        #pragma unroll
                        for (int tm = 0; tm < 2; ++tm) {
                            int tn = 2 * (nh * 2 + n2);
                            mma16816(acc[tm][tn],   ah[tm], bh[n2][0], bh[n2][2]);
                            mma16816(acc[tm][tn+1], ah[tm], bh[n2][1], bh[n2][3]);
                        }
                    // pass 2: A_hi x B_lo
                    #pragma unroll
                    for (int n2 = 0; n2 < 2; ++n2)
                        #pragma unroll
                        for (int tm = 0; tm < 2; ++tm) {
                            int tn = 2 * (nh * 2 + n2);
                            mma16816(acc[tm][tn],   ah[tm], bl[n2][0], bl[n2][2]);
                            mma16816(acc[tm][tn+1], ah[tm], bl[n2][1], bl[n2][3]);
                        }
                    // pass 3: A_lo x B_hi
                    #pragma unroll
                    for (int n2 = 0; n2 < 2; ++n2)
                        #pragma unroll
                        for (int tm = 0; tm < 2; ++tm) {
                            int tn = 2 * (nh * 2 + n2);
                            mma16816(acc[tm][tn],   al[tm], bh[n2][0], bh[n2][2]);
                            mma16816(acc[tm][tn+1], al[tm], bh[n2][1], bh[n2][3]);
                        }
                }
            }
        }
    }
    __syncthreads();                           // last mma done before overlay

    // ---- store accumulators to gate planes [nb][128][68] ----
    {
        float* plane = (float*)(smem + nb * PLANE_B);
        int r0 = lane >> 2, c0 = (lane & 3) * 2;
        #pragma unroll
        for (int tm = 0; tm < 2; ++tm)
            #pragma unroll
            for (int tn = 0; tn < 8; ++tn) {
                int mrow = m0 + tm * 16 + r0;
                int ncol = tn * 8 + c0;
                *(float2*)(plane + mrow * 68 + ncol) =
                    make_float2(acc[tm][tn][0], acc[tm][tn][1]);
                *(float2*)(plane + (mrow + 8) * 68 + ncol) =
                    make_float2(acc[tm][tn][2], acc[tm][tn][3]);
            }
    }
    __syncthreads();

    // ---- fused GRU epilogue: thread -> (row m = t>>2, 16 dims) ----
    const int m = t >> 2;
    const int dl0 = (t & 3) * 16;
    const int mg = rowBase + m;
    const bool valid = (mg < M);
    float ho16[16], hp16[16];
    if (valid) {
        rsplit16(Ab + (size_t)mg * 1024 + 512 + (size_t)(d0g + dl0) * 2, hp16);
        const float* pf = (const float*)smem;
        const float* bs = (const float*)(smem + SM_BIAS);
        #pragma unroll
        for (int q4 = 0; q4 < 4; ++q4) {
            int dl = dl0 + q4 * 4;
            const float* p0 = pf + m * 68 + dl;
            float4 vr  = *(const float4*)(p0);
            float4 vz  = *(const float4*)(p0 + PLANE_F);
            float4 vni = *(const float4*)(p0 + 2 * PLANE_F);
            float4 vnh = *(const float4*)(p0 + 3 * PLANE_F);
            float ar[4] = {vr.x, vr.y, vr.z, vr.w};
            float az[4] = {vz.x, vz.y, vz.z, vz.w};
            float ai[4] = {vni.x, vni.y, vni.z, vni.w};
            float ah[4] = {vnh.x, vnh.y, vnh.z, vnh.w};
            #pragma unroll
            for (int e = 0; e < 4; ++e) {
                int dq = dl + e;
                float r = sigacc(ar[e] + bs[dq]);
                float z = sigacc(az[e] + bs[64 + dq]);
                float nv = tanhacc(ai[e] + bs[128 + dq] + r * (ah[e] + bs[192 + dq]));
                ho16[q4 * 4 + e] = (1.f - z) * nv + z * hp16[q4 * 4 + e];
            }
        }
    }

    if (MODE == 0) {
        if (valid)
            wsplit16((char*)Hw + (size_t)mg * 1024 + 512 + (size_t)(d0g + dl0) * 2,
                     ho16);
    } else {
        float e16[16];
        if (valid) {
            #pragma unroll
            for (int q = 0; q < 16; ++q) e16[q] = 0.5f * (hp16[q] + ho16[q]);
            if (embOut) {
                #pragma unroll
                for (int q4 = 0; q4 < 4; ++q4)
                    *(float4*)(embOut + (size_t)mg * 256 + d0g + dl0 + q4 * 4) =
                        make_float4(e16[q4*4], e16[q4*4+1], e16[q4*4+2], e16[q4*4+3]);
            }
        }
        if (A1n) {
            float* hop = (float*)(smem + SM_HOPL);
            if (valid) {
                // emb' -> next-level x-part
                __nv_bfloat16* dstA = (m & 1) ? A2n : A1n;
                wsplit16((char*)dstA + (size_t)(mg >> 1) * 1024 +
                         (size_t)(d0g + dl0) * 2, e16);
                // stage h2 for pair exchange
                #pragma unroll
                for (int q4 = 0; q4 < 4; ++q4)
                    *(float4*)(hop + m * 68 + dl0 + q4 * 4) =
                        make_float4(ho16[q4*4], ho16[q4*4+1], ho16[q4*4+2], ho16[q4*4+3]);
            }
            __syncthreads();
            if (valid && !(m & 1)) {
                float h016[16];
                #pragma unroll
                for (int q4 = 0; q4 < 4; ++q4) {
                    float4 v = *(const float4*)(hop + (m + 1) * 68 + dl0 + q4 * 4);
                    h016[q4*4]   = 0.5f * (ho16[q4*4]   + v.x);
                    h016[q4*4+1] = 0.5f * (ho16[q4*4+1] + v.y);
                    h016[q4*4+2] = 0.5f * (ho16[q4*4+2] + v.z);
                    h016[q4*4+3] = 0.5f * (ho16[q4*4+3] + v.w);
                }
                wsplit16((char*)A1n + (size_t)(mg >> 1) * 1024 + 512 +
                         (size_t)(d0g + dl0) * 2, h016);
            }
        }
    }
#undef STAGE
}

// ---------------- driver ----------------
extern "C" void kernel_launch(void* const* d_in, const int* in_sizes, int n_in,
                              void* d_out, int out_size) {
    (void)in_sizes; (void)n_in; (void)out_size;
    const float* leaf = (const float*)d_in[0];
    const float* Wih  = (const float*)d_in[1];
    const float* Whh  = (const float*)d_in[2];
    const float* bih  = (const float*)d_in[3];
    const float* bhh  = (const float*)d_in[4];
    float* out = (float*)d_out;

    __nv_bfloat16 *A1, *A2a, *A2b;
    cudaGetSymbolAddress((void**)&A1, g_A1);
    cudaGetSymbolAddress((void**)&A2a, g_A2a);
    cudaGetSymbolAddress((void**)&A2b, g_A2b);

    cudaFuncSetAttribute(gemm_cell<0>, cudaFuncAttributeMaxDynamicSharedMemorySize, SM_TOTAL);
    cudaFuncSetAttribute(gemm_cell<1>, cudaFuncAttributeMaxDynamicSharedMemorySize, SM_TOTAL);

    wprep<<<(4 * 192 * 512 + 255) / 256, 256>>>(Wih, Whh);
    prep0<<<(65536 * 128) / 256, 256>>>(leaf, 65536);

    __nv_bfloat16* A2cur = A2a;
    for (int lvl = 0; lvl < 12; ++lvl) {
        int M = 32 << (11 - lvl);
        dim3 grid((M + 127) / 128, 4);
        // cell1: reads A1 (x=xL, h=h0); writes h1 split into A2cur h-part
        gemm_cell<0><<<grid, 512, SM_TOTAL>>>(A1, bih, bhh, A2cur,
                                              nullptr, nullptr, nullptr, M);
        // cell2: reads A2cur (x=xR, h=h1); writes next-level A1/A2next (+ out)
        __nv_bfloat16* A2next = (A2cur == A2a) ? A2b : A2a;
        bool last = (lvl == 11);
        gemm_cell<1><<<grid, 512, SM_TOTAL>>>(A2cur, bih, bhh, nullptr,
                                              last ? nullptr : A1,
                                              last ? nullptr : A2next,
                                              last ? out : nullptr, M);
        A2cur = A2next;
    }
}

// round 13
// speedup vs baseline: 1.3738x; 1.3738x over previous
#include <cuda_runtime.h>
#include <cuda_fp16.h>
#include <cstdint>
#include <math.h>

// ============================================================================
// Tree-GRU via mma.sync fp16 2-term GEMMs.  B=32, L=4096, D=256.
// A (fp16 hi) x [Whi (f32-acc) + Wlo (f16-acc)].  GRU state carried in fp32
// side buffers; fp16 copies only feed the GEMM.
// Gate warps (nb): r(all K), z(all K), i_n(K<256), h_n(K>=256).
// R11: identical to R10 (infra failure); smem layout verified:
//   staging 0..131072 | gate planes 0..139264 (overlay) | hop 139264..174080
//   | bias 174080..175104 = SM_TOTAL.
// ============================================================================

#define DH 256
#define MROWS_MAX 65536
#define ASTRIDE ((size_t)MROWS_MAX * 512)          // fp16 elems (single term)
#define WSTRIDE ((size_t)4 * 192 * 512)
#define WBYTES  (WSTRIDE * 2)

__device__ __half g_A1[ASTRIDE];     // [m][512]: x | h
__device__ __half g_A2a[ASTRIDE];
__device__ __half g_A2b[ASTRIDE];
__device__ __half g_Wb[2 * WSTRIDE]; // [term][dblk][192][512]
__device__ float g_H1[MROWS_MAX * DH];   // h1 fp32
__device__ float g_H0a[MROWS_MAX * DH];  // h0 fp32 ping
__device__ float g_H0b[MROWS_MAX * DH];  // h0 fp32 pong

// ---------------- PTX helpers ----------------
__device__ __forceinline__ uint32_t smem_u32(const void* p) {
    uint32_t a;
    asm("{ .reg .u64 t; cvta.to.shared.u64 t, %1; cvt.u32.u64 %0, t; }"
        : "=r"(a) : "l"(p));
    return a;
}
__device__ __forceinline__ void cpasync16(uint32_t dst, const void* src) {
    asm volatile("cp.async.cg.shared.global [%0], [%1], 16;"
                 :: "r"(dst), "l"(src) : "memory");
}
__device__ __forceinline__ void cpcommit() {
    asm volatile("cp.async.commit_group;" ::: "memory");
}
template<int N>
__device__ __forceinline__ void cpwait() {
    asm volatile("cp.async.wait_group %0;" :: "n"(N) : "memory");
}
__device__ __forceinline__ void ldsm4(uint32_t r[4], uint32_t addr) {
    asm volatile("ldmatrix.sync.aligned.m8n8.x4.shared.b16 {%0,%1,%2,%3}, [%4];"
                 : "=r"(r[0]), "=r"(r[1]), "=r"(r[2]), "=r"(r[3]) : "r"(addr));
}
// f32-accumulate fp16 mma (big term)
__device__ __forceinline__ void mmaF(float c[4], const uint32_t a[4],
                                     uint32_t b0, uint32_t b1) {
    asm("mma.sync.aligned.m16n8k16.row.col.f32.f16.f16.f32 "
        "{%0,%1,%2,%3}, {%4,%5,%6,%7}, {%8,%9}, {%0,%1,%2,%3};"
        : "+f"(c[0]), "+f"(c[1]), "+f"(c[2]), "+f"(c[3])
        : "r"(a[0]), "r"(a[1]), "r"(a[2]), "r"(a[3]),
          "r"(b0), "r"(b1));
}
// f16-accumulate fp16 mma (small correction term; 2x rate if HW splits rates)
__device__ __forceinline__ void mmaH(uint32_t c[2], const uint32_t a[4],
                                     uint32_t b0, uint32_t b1) {
    asm("mma.sync.aligned.m16n8k16.row.col.f16.f16.f16.f16 "
        "{%0,%1}, {%2,%3,%4,%5}, {%6,%7}, {%0,%1};"
        : "+r"(c[0]), "+r"(c[1])
        : "r"(a[0]), "r"(a[1]), "r"(a[2]), "r"(a[3]),
          "r"(b0), "r"(b1));
}
#define SW64(x) ((x) ^ (((x) >> 3) & 0x30))

// ---------------- math helpers ----------------
__device__ __forceinline__ float sigacc(float x) { return 1.f / (1.f + expf(-x)); }
__device__ __forceinline__ float tanhacc(float x) {
    float ax = fabsf(x);
    float t = expf(-2.f * ax);
    float r = (1.f - t) / (1.f + t);
    return (x < 0.f) ? -r : r;
}
__device__ __forceinline__ uint32_t pkh2(float a, float b) {
    __half2 h = __floats2half2_rn(a, b);
    return *(uint32_t*)&h;
}
// write 16 f32 values as 16 fp16 (32 bytes)
__device__ __forceinline__ void whalf16(char* p, const float* v) {
    #pragma unroll
    for (int h = 0; h < 2; ++h) {
        uint4 o;
        o.x = pkh2(v[h * 8 + 0], v[h * 8 + 1]);
        o.y = pkh2(v[h * 8 + 2], v[h * 8 + 3]);
        o.z = pkh2(v[h * 8 + 4], v[h * 8 + 5]);
        o.w = pkh2(v[h * 8 + 6], v[h * 8 + 7]);
        *(uint4*)(p + h * 16) = o;
    }
}

// ---------------- weight prep: g_Wb[term][dblk][gate*64+dd][k] ----------------
__global__ void wprep(const float* __restrict__ wih, const float* __restrict__ whh) {
    int idx = blockIdx.x * blockDim.x + threadIdx.x;
    if (idx >= 4 * 192 * 512) return;
    int k = idx & 511;
    int rowall = idx >> 9;
    int blk = rowall / 192;
    int rr = rowall - blk * 192;
    int gate = rr >> 6;
    int dd = rr & 63;
    int g = gate * 256 + blk * 64 + dd;
    float v = (k < 256) ? wih[g * 256 + k] : whh[g * 256 + (k - 256)];
    __half hi = __float2half_rn(v);
    __half lo = __float2half_rn(v - __half2float(hi));
    g_Wb[idx] = hi;
    g_Wb[WSTRIDE + idx] = lo;
}

// ---------------- level-0 prep: leaf -> A1 (xL, h=0), A2a (xR) ----------------
__global__ void prep0(const float* __restrict__ emb, int M) {
    int idx = blockIdx.x * blockDim.x + threadIdx.x;   // M*128
    if (idx >= M * 128) return;
    int m = idx >> 7;
    int kq = idx & 127;
    size_t rowL = ((size_t)(2 * m)) * 256;
    char* A1 = (char*)g_A1;
    char* A2 = (char*)g_A2a;
    if (kq < 64) {
        int k = kq * 4;
        float4 xl = *(const float4*)(emb + rowL + k);
        float4 xr = *(const float4*)(emb + rowL + 256 + k);
        size_t off = (size_t)m * 1024 + (size_t)k * 2;
        *(uint2*)(A1 + off) = make_uint2(pkh2(xl.x, xl.y), pkh2(xl.z, xl.w));
        *(uint2*)(A2 + off) = make_uint2(pkh2(xr.x, xr.y), pkh2(xr.z, xr.w));
    } else {
        int k = (kq - 64) * 4;
        *(uint2*)(A1 + (size_t)m * 1024 + 512 + (size_t)k * 2) = make_uint2(0u, 0u);
    }
}

// ---------------- GEMM cell kernel ----------------
// smem: 4 staging buffers x 32768B (A 8K | Whi 12K | Wlo 12K) = 131072.
// Epilogue overlays: 4 gate planes [128][68] f32 at 0 (139264 bytes),
// ho plane at 139264 (34816 bytes, ends 174080), bias at 174080 (1024).
#define SM_BUFSZ 32768
#define PLANE_B 34816
#define PLANE_F 8704
#define SM_HOPL 139264
#define SM_BIAS 174080
#define SM_TOTAL 175104

template<int MODE>
__global__ __launch_bounds__(512, 1) void gemm_cell(
    const __half* __restrict__ Abase,
    const float* __restrict__ Hp,              // fp32 prev state (null @lvl0 cell1)
    const float* __restrict__ bih, const float* __restrict__ bhh,
    __half* __restrict__ Hw,                   // MODE0: h1 fp16 -> A2cur h-part
    float* __restrict__ H1w,                   // MODE0: h1 fp32 out
    __half* __restrict__ A1n,                  // MODE1: next-level A1
    __half* __restrict__ A2n,                  // MODE1: next-level A2
    float* __restrict__ H0n,                   // MODE1: next-level h0 fp32
    float* __restrict__ embOut,                // MODE1 level 11 only
    int M)
{
    extern __shared__ char smem[];
    const uint32_t sbt = smem_u32(smem);
    const int t = threadIdx.x;
    const int lane = t & 31, wid = t >> 5;
    const int mi = wid & 3, nb = wid >> 2;     // nb: 0=r 1=z 2=i_n 3=h_n
    const int rowBase = blockIdx.x * 128;
    const int dblk = blockIdx.y;
    const int d0g = dblk * 64;
    const char* Ab = (const char*)Abase;

    if (t < 64) {
        int dg = d0g + t;
        float* bs = (float*)(smem + SM_BIAS);
        bs[t]       = bih[dg] + bhh[dg];
        bs[64 + t]  = bih[256 + dg] + bhh[256 + dg];
        bs[128 + t] = bih[512 + dg];
        bs[192 + t] = bhh[512 + dg];
    }

    // ---- staging precompute: 4 x 16B slots/thread (2048 total per chunk) ----
    const char* sA;
    const char* sW;
    uint32_t dstA, dW0, dW1, dW2;
    int wd1, wd2;
    {
        int row = t >> 2, seg = t & 3;
        sA = Ab + (size_t)(rowBase + row) * 1024 + seg * 16;
        dstA = SW64(row * 64 + seg * 16);
        long woff[3];
        uint32_t dws[3];
        #pragma unroll
        for (int p = 0; p < 3; ++p) {
            int idx = t + 512 * p;
            int term = (idx >= 768) ? 1 : 0;
            int rem = idx - term * 768;
            int wr = rem >> 2, ws = rem & 3;
            woff[p] = (long)term * WBYTES + (long)(dblk * 192 + wr) * 1024 + ws * 16;
            dws[p] = 8192 + term * 12288 + SW64(wr * 64 + ws * 16);
        }
        sW = (const char*)g_Wb + woff[0];
        wd1 = (int)(woff[1] - woff[0]);
        wd2 = (int)(woff[2] - woff[0]);
        dW0 = dws[0]; dW1 = dws[1]; dW2 = dws[2];
    }
#define STAGE(bi) do { uint32_t bb = sbt + (bi) * SM_BUFSZ;           \
        cpasync16(bb + dstA, sA); sA += 64;                            \
        cpasync16(bb + dW0, sW);                                       \
        cpasync16(bb + dW1, sW + wd1);                                 \
        cpasync16(bb + dW2, sW + wd2); sW += 64; } while (0)

    // ---- ldsm address precompute ----
    const int rsel = lane & 15, half = lane >> 4;
    const int m0 = mi * 32;
    const int wrow = (nb >= 2) ? 128 : nb * 64;
    const int rA0 = m0 + rsel,      aoff0 = rA0 * 64, ax0 = (rA0 >> 1) & 3;
    const int rA1 = m0 + 16 + rsel, aoff1 = rA1 * 64, ax1 = (rA1 >> 1) & 3;
    int boff[4], bx[4];
    #pragma unroll
    for (int n16 = 0; n16 < 4; ++n16) {
        int rB = wrow + n16 * 16 + rsel;
        boff[n16] = rB * 64;
        bx[n16] = (rB >> 1) & 3;
    }

    float accF[2][8][4];
    uint32_t accH[2][8][2];
    #pragma unroll
    for (int a = 0; a < 2; ++a)
        #pragma unroll
        for (int b = 0; b < 8; ++b) {
            #pragma unroll
            for (int e = 0; e < 4; ++e) accF[a][b][e] = 0.f;
            accH[a][b][0] = 0u; accH[a][b][1] = 0u;
        }

    STAGE(0); cpcommit();
    STAGE(1); cpcommit();
    STAGE(2); cpcommit();

    for (int c = 0; c < 16; ++c) {
        __syncthreads();                       // buf (c-1)&3 readers done
        if (c < 13) STAGE((c + 3) & 3);
        cpcommit();
        cpwait<3>();
        __syncthreads();                       // chunk c visible to all
        bool act = (nb < 2) || (nb == 2 && c < 8) || (nb == 3 && c >= 8);
        if (act) {
            uint32_t bb = sbt + (c & 3) * SM_BUFSZ;
            uint32_t bA = bb, bW = bb + 8192, bWl = bb + 20480;
            #pragma unroll
            for (int kb = 0; kb < 2; ++kb) {
                int sg = 2 * kb + half;
                uint32_t ah[2][4];
                ldsm4(ah[0], bA + aoff0 + ((sg ^ ax0) << 4));
                ldsm4(ah[1], bA + aoff1 + ((sg ^ ax1) << 4));
                #pragma unroll
                for (int n16 = 0; n16 < 4; ++n16) {
                    uint32_t bh[4], bl[4];
                    uint32_t wo = ((sg ^ bx[n16]) << 4) + boff[n16];
                    ldsm4(bh, bW + wo);
                    ldsm4(bl, bWl + wo);
                    #pragma unroll
                    for (int tm = 0; tm < 2; ++tm) {
                        mmaF(accF[tm][2*n16],   ah[tm], bh[0], bh[2]);
                        mmaF(accF[tm][2*n16+1], ah[tm], bh[1], bh[3]);
                    }
                    #pragma unroll
                    for (int tm = 0; tm < 2; ++tm) {
                        mmaH(accH[tm][2*n16],   ah[tm], bl[0], bl[2]);
                        mmaH(accH[tm][2*n16+1], ah[tm], bl[1], bl[3]);
                    }
                }
            }
        }
    }
    __syncthreads();                           // last mma done before overlay

    // ---- store accumulators (F + cvt(H)) to gate planes [nb][128][68] ----
    {
        float* plane = (float*)(smem + nb * PLANE_B);
        int r0 = lane >> 2, c0 = (lane & 3) * 2;
        #pragma unroll
        for (int tm = 0; tm < 2; ++tm)
            #pragma unroll
            for (int tn = 0; tn < 8; ++tn) {
                __half2 h01 = *(__half2*)&accH[tm][tn][0];
                __half2 h23 = *(__half2*)&accH[tm][tn][1];
                float2 f01 = __half22float2(h01);
                float2 f23 = __half22float2(h23);
                int mrow = m0 + tm * 16 + r0;
                int ncol = tn * 8 + c0;
                *(float2*)(plane + mrow * 68 + ncol) =
                    make_float2(accF[tm][tn][0] + f01.x, accF[tm][tn][1] + f01.y);
                *(float2*)(plane + (mrow + 8) * 68 + ncol) =
                    make_float2(accF[tm][tn][2] + f23.x, accF[tm][tn][3] + f23.y);
            }
    }
    __syncthreads();

    // ---- fused GRU epilogue: thread -> (row m = t>>2, 16 dims) ----
    const int m = t >> 2;
    const int dl0 = (t & 3) * 16;
    const int mg = rowBase + m;
    const bool valid = (mg < M);
    float ho16[16], hp16[16];
    if (valid) {
        if (Hp) {
            #pragma unroll
            for (int q4 = 0; q4 < 4; ++q4) {
                float4 v = *(const float4*)(Hp + (size_t)mg * 256 + d0g + dl0 + q4 * 4);
                hp16[q4*4] = v.x; hp16[q4*4+1] = v.y;
                hp16[q4*4+2] = v.z; hp16[q4*4+3] = v.w;
            }
        } else {
            #pragma unroll
            for (int q = 0; q < 16; ++q) hp16[q] = 0.f;
        }
        const float* pf = (const float*)smem;
        const float* bs = (const float*)(smem + SM_BIAS);
        #pragma unroll
        for (int q4 = 0; q4 < 4; ++q4) {
            int dl = dl0 + q4 * 4;
            const float* p0 = pf + m * 68 + dl;
            float4 vr  = *(const float4*)(p0);
            float4 vz  = *(const float4*)(p0 + PLANE_F);
            float4 vni = *(const float4*)(p0 + 2 * PLANE_F);
            float4 vnh = *(const float4*)(p0 + 3 * PLANE_F);
            float ar[4] = {vr.x, vr.y, vr.z, vr.w};
            float az[4] = {vz.x, vz.y, vz.z, vz.w};
            float ai[4] = {vni.x, vni.y, vni.z, vni.w};
            float ah[4] = {vnh.x, vnh.y, vnh.z, vnh.w};
            #pragma unroll
            for (int e = 0; e < 4; ++e) {
                int dq = dl + e;
                float r = sigacc(ar[e] + bs[dq]);
                float z = sigacc(az[e] + bs[64 + dq]);
                float nv = tanhacc(ai[e] + bs[128 + dq] + r * (ah[e] + bs[192 + dq]));
                ho16[q4 * 4 + e] = (1.f - z) * nv + z * hp16[q4 * 4 + e];
            }
        }
    }

    if (MODE == 0) {
        if (valid) {
            whalf16((char*)Hw + (size_t)mg * 1024 + 512 + (size_t)(d0g + dl0) * 2,
                    ho16);
            #pragma unroll
            for (int q4 = 0; q4 < 4; ++q4)
                *(float4*)(H1w + (size_t)mg * 256 + d0g + dl0 + q4 * 4) =
                    make_float4(ho16[q4*4], ho16[q4*4+1], ho16[q4*4+2], ho16[q4*4+3]);
        }
    } else {
        float e16[16];
        if (valid) {
            #pragma unroll
            for (int q = 0; q < 16; ++q) e16[q] = 0.5f * (hp16[q] + ho16[q]);
            if (embOut) {
                #pragma unroll
                for (int q4 = 0; q4 < 4; ++q4)
                    *(float4*)(embOut + (size_t)mg * 256 + d0g + dl0 + q4 * 4) =
                        make_float4(e16[q4*4], e16[q4*4+1], e16[q4*4+2], e16[q4*4+3]);
            }
        }
        if (A1n) {
            float* hop = (float*)(smem + SM_HOPL);
            if (valid) {
                __half* dstA = (m & 1) ? A2n : A1n;
                whalf16((char*)dstA + (size_t)(mg >> 1) * 1024 +
                        (size_t)(d0g + dl0) * 2, e16);
                #pragma unroll
                for (int q4 = 0; q4 < 4; ++q4)
                    *(float4*)(hop + m * 68 + dl0 + q4 * 4) =
                        make_float4(ho16[q4*4], ho16[q4*4+1], ho16[q4*4+2], ho16[q4*4+3]);
            }
            __syncthreads();
            if (valid && !(m & 1)) {
                float h016[16];
                #pragma unroll
                for (int q4 = 0; q4 < 4; ++q4) {
                    float4 v = *(const float4*)(hop + (m + 1) * 68 + dl0 + q4 * 4);
                    h016[q4*4]   = 0.5f * (ho16[q4*4]   + v.x);
                    h016[q4*4+1] = 0.5f * (ho16[q4*4+1] + v.y);
                    h016[q4*4+2] = 0.5f * (ho16[q4*4+2] + v.z);
                    h016[q4*4+3] = 0.5f * (ho16[q4*4+3] + v.w);
                }
                whalf16((char*)A1n + (size_t)(mg >> 1) * 1024 + 512 +
                        (size_t)(d0g + dl0) * 2, h016);
                #pragma unroll
                for (int q4 = 0; q4 < 4; ++q4)
                    *(float4*)(H0n + (size_t)(mg >> 1) * 256 + d0g + dl0 + q4 * 4) =
                        make_float4(h016[q4*4], h016[q4*4+1], h016[q4*4+2], h016[q4*4+3]);
            }
        }
    }
#undef STAGE
}

// ---------------- driver ----------------
extern "C" void kernel_launch(void* const* d_in, const int* in_sizes, int n_in,
                              void* d_out, int out_size) {
    (void)in_sizes; (void)n_in; (void)out_size;
    const float* leaf = (const float*)d_in[0];
    const float* Wih  = (const float*)d_in[1];
    const float* Whh  = (const float*)d_in[2];
    const float* bih  = (const float*)d_in[3];
    const float* bhh  = (const float*)d_in[4];
    float* out = (float*)d_out;

    __half *A1, *A2a, *A2b;
    float *H1, *H0a, *H0b;
    cudaGetSymbolAddress((void**)&A1, g_A1);
    cudaGetSymbolAddress((void**)&A2a, g_A2a);
    cudaGetSymbolAddress((void**)&A2b, g_A2b);
    cudaGetSymbolAddress((void**)&H1, g_H1);
    cudaGetSymbolAddress((void**)&H0a, g_H0a);
    cudaGetSymbolAddress((void**)&H0b, g_H0b);

    cudaFuncSetAttribute(gemm_cell<0>, cudaFuncAttributeMaxDynamicSharedMemorySize, SM_TOTAL);
    cudaFuncSetAttribute(gemm_cell<1>, cudaFuncAttributeMaxDynamicSharedMemorySize, SM_TOTAL);

    wprep<<<(4 * 192 * 512 + 255) / 256, 256>>>(Wih, Whh);
    prep0<<<(65536 * 128) / 256, 256>>>(leaf, 65536);

    __half* A2cur = A2a;
    const float* H0cur = nullptr;
    for (int lvl = 0; lvl < 12; ++lvl) {
        int M = 32 << (11 - lvl);
        dim3 grid((M + 127) / 128, 4);
        // cell1: A1 (xL | h0) -> h1 (fp16 into A2cur h-part, fp32 into H1)
        gemm_cell<0><<<grid, 512, SM_TOTAL>>>(A1, H0cur, bih, bhh, A2cur, H1,
                                              nullptr, nullptr, nullptr, nullptr, M);
        // cell2: A2cur (xR | h1) -> next level A1/A2, h0 fp32 (+ out @lvl11)
        __half* A2next = (A2cur == A2a) ? A2b : A2a;
        float* H0n = (H0cur == H0a) ? H0b : H0a;
        bool last = (lvl == 11);
        gemm_cell<1><<<grid, 512, SM_TOTAL>>>(A2cur, H1, bih, bhh,
                                              nullptr, nullptr,
                                              last ? nullptr : A1,
                                              last ? nullptr : A2next,
                                              last ? nullptr : H0n,
                                              last ? out : nullptr, M);
        A2cur = A2next;
        H0cur = H0n;
    }
}